// round 9
// baseline (speedup 1.0000x reference)
#include <cuda_runtime.h>
#include <cstdint>

#define B_      16
#define C_      3
#define HW_     (512 * 512)
#define HW4_    (HW_ / 4)              /* 65536 float4 vectors per image */
#define NCLS    64
#define NSEG    (B_ * NCLS)
#define STRIDE  32                     /* u64 elems -> 256 B bin stride */
#define NBLKX   27                     /* blocks per image */
#define NBLK    (NBLKX * B_)           /* 432 */
#define THREADS 128
#define NWARP   4
#define ROWS_PER_IMG 512               /* HW4_ / 128 stage-rows */

#define HIST_BYTES   (NWARP * NCLS * 32 * 4)          /* 32768 */
#define NSTREAM      7
#define STREAM_PITCH (THREADS * 16)                   /* 2048 B per stream */
#define STAGE_BYTES  (NSTREAM * STREAM_PITCH)         /* 14336 */
#define SMEM_TOTAL   (HIST_BYTES + 2 * STAGE_BYTES)   /* 61440 -> 3 blocks/SM */

#define PLANE_BYTES  (HW_ * 4)         /* 1 MiB per channel plane */

__device__ unsigned long long d_bins[NSEG * STRIDE];
__device__ unsigned int       d_ticket;

// global packed u64: count [44:64), sum * 2^20 in [0:44)
#define GSCALE  1048576.0f
#define GINV    (1.0f / 1048576.0f)
#define GMASK   ((1ull << 44) - 1ull)
// shared packed u32 per lane-private slot (<=76 px/slot):
//   count [25:32) (max 127), sum * 2^12 in [0:25)
#define LSCALE  4096.0f
#define LCNT    (1u << 25)
#define LMASK   ((1u << 25) - 1u)
#define L2G     (GSCALE / LSCALE)

// ---- minimal mbarrier / TMA-1D-bulk wrappers ----
__device__ __forceinline__ void mbar_init(uint32_t a, uint32_t cnt) {
    asm volatile("mbarrier.init.shared.b64 [%0], %1;" :: "r"(a), "r"(cnt) : "memory");
}
__device__ __forceinline__ void mbar_expect_tx(uint32_t a, uint32_t tx) {
    asm volatile("mbarrier.arrive.expect_tx.shared.b64 _, [%0], %1;"
                 :: "r"(a), "r"(tx) : "memory");
}
__device__ __forceinline__ void mbar_arrive(uint32_t a) {
    asm volatile("mbarrier.arrive.shared.b64 _, [%0];" :: "r"(a) : "memory");
}
__device__ __forceinline__ void mbar_wait(uint32_t a, uint32_t ph) {
    uint32_t done;
    asm volatile(
        "{\n\t.reg .pred p;\n\t"
        "mbarrier.try_wait.parity.acquire.cta.shared::cta.b64 p, [%1], %2;\n\t"
        "selp.b32 %0, 1, 0, p;\n\t}"
        : "=r"(done) : "r"(a), "r"(ph) : "memory");
    if (!done) {
        asm volatile(
            "{\n\t.reg .pred P1;\n\t"
            "W_%=:\n\t"
            "mbarrier.try_wait.parity.acquire.cta.shared::cta.b64 P1, [%0], %1, 0x989680;\n\t"
            "@P1 bra.uni D_%=;\n\t"
            "bra.uni W_%=;\n\t"
            "D_%=:\n\t}"
            :: "r"(a), "r"(ph) : "memory");
    }
}
__device__ __forceinline__ void tma1d(uint32_t dst, const void* src, uint32_t mbar) {
    asm volatile(
        "cp.async.bulk.shared::cta.global.mbarrier::complete_tx::bytes [%0], [%1], %2, [%3];"
        :: "r"(dst), "l"(src), "r"((uint32_t)STREAM_PITCH), "r"(mbar) : "memory");
}
__device__ __forceinline__ void fence_async_proxy() {
    asm volatile("fence.proxy.async.shared::cta;" ::: "memory");
}

__global__ void __launch_bounds__(THREADS)
fused_kernel(const float* __restrict__ inp,
             const float* __restrict__ tgt,
             const int*   __restrict__ msk,
             float*       __restrict__ out)
{
    extern __shared__ char smem_raw[];
    uint32_t* hist    = (uint32_t*)smem_raw;              // [NWARP][NCLS][32]
    char*     stage_g = smem_raw + HIST_BYTES;
    const uint32_t stage_s =
        (uint32_t)__cvta_generic_to_shared(smem_raw) + HIST_BYTES;

    __shared__ unsigned long long mbar[4];   // full0, full1, empty0, empty1
    __shared__ float    s_sum[2][NCLS];
    __shared__ uint32_t s_cnt[2][NCLS];
    __shared__ float    rtot[4], rws[4], rmx[4];
    __shared__ unsigned int s_ticket;
    const uint32_t mb = (uint32_t)__cvta_generic_to_shared(mbar);

    const int t    = threadIdx.x;
    const int wid  = t >> 5;
    const int lane = t & 31;
    const int b    = blockIdx.y;
    const int x    = blockIdx.x;

    const char* ipc = (const char*)(inp + (size_t)b * C_ * HW_);
    const char* tpc = (const char*)(tgt + (size_t)b * C_ * HW_);
    const char* mpc = (const char*)(msk + (size_t)b * HW_);

    // exact stage-row tiling: 512 rows = 26 blocks * 19 + 1 block * 18
    const int row0 = x * 19;
    const int nk   = (x < 26) ? 19 : 18;

    if (t == 0) {
        mbar_init(mb + 0,  1);        // full0  (expect_tx arrival)
        mbar_init(mb + 8,  1);        // full1
        mbar_init(mb + 16, THREADS);  // empty0
        mbar_init(mb + 24, THREADS);  // empty1
    }
    // zero hist (2048 uint4 / 128 threads)
    {
        uint4* hz = (uint4*)hist;
#pragma unroll
        for (int i = 0; i < (NWARP * NCLS * 32) / (4 * THREADS); i++)
            hz[i * THREADS + t] = make_uint4(0u, 0u, 0u, 0u);
    }
    __syncthreads();

#define ISSUE_STAGE(s, buf)                                                   \
    do {                                                                      \
        const uint32_t _d  = stage_s + (buf) * STAGE_BYTES;                   \
        const size_t   _o  = (size_t)(row0 + (s)) * 2048;                     \
        mbar_expect_tx(mb + (buf) * 8, STAGE_BYTES);                          \
        tma1d(_d + 0 * STREAM_PITCH, ipc + _o,                  mb + (buf)*8);\
        tma1d(_d + 1 * STREAM_PITCH, ipc + PLANE_BYTES + _o,    mb + (buf)*8);\
        tma1d(_d + 2 * STREAM_PITCH, ipc + 2*PLANE_BYTES + _o,  mb + (buf)*8);\
        tma1d(_d + 3 * STREAM_PITCH, tpc + _o,                  mb + (buf)*8);\
        tma1d(_d + 4 * STREAM_PITCH, tpc + PLANE_BYTES + _o,    mb + (buf)*8);\
        tma1d(_d + 5 * STREAM_PITCH, tpc + 2*PLANE_BYTES + _o,  mb + (buf)*8);\
        tma1d(_d + 6 * STREAM_PITCH, mpc + _o,                  mb + (buf)*8);\
    } while (0)

    if (t == 0) {
        fence_async_proxy();          // order mbarrier init vs async proxy
        ISSUE_STAGE(0, 0);
        ISSUE_STAGE(1, 1);            // nk >= 18 always
    }

    uint32_t* mybins = hist + wid * (NCLS * 32) + lane;
    int fullPh0 = 0, fullPh1 = 0;
    int emptyPh0 = 0, emptyPh1 = 0;   // used by t0 only

    for (int k = 0; k < nk; k++) {
        const int buf = k & 1;
        if (buf == 0) { mbar_wait(mb + 0, fullPh0); fullPh0 ^= 1; }
        else          { mbar_wait(mb + 8, fullPh1); fullPh1 ^= 1; }

        const char* sp = stage_g + buf * STAGE_BYTES + t * 16;
        const float4 a0 = *(const float4*)(sp + 0 * STREAM_PITCH);
        const float4 a1 = *(const float4*)(sp + 1 * STREAM_PITCH);
        const float4 a2 = *(const float4*)(sp + 2 * STREAM_PITCH);
        const float4 c0 = *(const float4*)(sp + 3 * STREAM_PITCH);
        const float4 c1 = *(const float4*)(sp + 4 * STREAM_PITCH);
        const float4 c2 = *(const float4*)(sp + 5 * STREAM_PITCH);
        const int4   m  = *(const int4*)  (sp + 6 * STREAM_PITCH);

        const float w0 = fabsf(a0.x - c0.x) + fabsf(a1.x - c1.x) + fabsf(a2.x - c2.x);
        const float w1 = fabsf(a0.y - c0.y) + fabsf(a1.y - c1.y) + fabsf(a2.y - c2.y);
        const float w2 = fabsf(a0.z - c0.z) + fabsf(a1.z - c1.z) + fabsf(a2.z - c2.z);
        const float w3 = fabsf(a0.w - c0.w) + fabsf(a1.w - c1.w) + fabsf(a2.w - c2.w);

        // lane-private RMW: bank(lane) constant -> conflict-free, no atomics
        mybins[(m.x & (NCLS - 1)) * 32] += LCNT + __float2uint_rn(w0 * LSCALE);
        mybins[(m.y & (NCLS - 1)) * 32] += LCNT + __float2uint_rn(w1 * LSCALE);
        mybins[(m.z & (NCLS - 1)) * 32] += LCNT + __float2uint_rn(w2 * LSCALE);
        mybins[(m.w & (NCLS - 1)) * 32] += LCNT + __float2uint_rn(w3 * LSCALE);

        mbar_arrive(mb + 16 + buf * 8);     // this buffer slot consumed

        if (t == 0 && k + 2 < nk) {
            // wait until ALL threads consumed stage k, then refill same buffer
            if (buf == 0) { mbar_wait(mb + 16, emptyPh0); emptyPh0 ^= 1; }
            else          { mbar_wait(mb + 24, emptyPh1); emptyPh1 ^= 1; }
            ISSUE_STAGE(k + 2, buf);
        }
    }
    __syncthreads();

    // ---- block flush: thread t reduces class (t&63) for warp-pair (t>>6) ----
    {
        const int c = t & 63;
        const int h = t >> 6;
        float    fs = 0.0f;
        uint32_t cc = 0u;
        const uint4* r0 = (const uint4*)(hist + (2 * h)     * (NCLS * 32) + c * 32);
        const uint4* r1 = (const uint4*)(hist + (2 * h + 1) * (NCLS * 32) + c * 32);
#pragma unroll
        for (int i = 0; i < 8; i++) {
            const int q = (i + (t & 7)) & 7;   // rotated quad -> spread banks
            const uint4 p0 = r0[q];
            const uint4 p1 = r1[q];
            cc += (p0.x >> 25) + (p0.y >> 25) + (p0.z >> 25) + (p0.w >> 25)
                + (p1.x >> 25) + (p1.y >> 25) + (p1.z >> 25) + (p1.w >> 25);
            fs += (float)(p0.x & LMASK) + (float)(p0.y & LMASK)
                + (float)(p0.z & LMASK) + (float)(p0.w & LMASK)
                + (float)(p1.x & LMASK) + (float)(p1.y & LMASK)
                + (float)(p1.z & LMASK) + (float)(p1.w & LMASK);
        }
        s_sum[h][c] = fs;
        s_cnt[h][c] = cc;
    }
    __syncthreads();

    if (t < NCLS) {
        const float    fs = s_sum[0][t] + s_sum[1][t];
        const uint32_t cc = s_cnt[0][t] + s_cnt[1][t];
        if (cc)
            atomicAdd(&d_bins[(size_t)(b * NCLS + t) * STRIDE],
                      ((unsigned long long)cc << 44) + __float2ull_rn(fs * L2G));
    }

    // ---- last-block finalize (fused) ----
    __threadfence();
    __syncthreads();
    if (t == 0) s_ticket = atomicAdd(&d_ticket, 1u);
    __syncthreads();
    if (s_ticket != NBLK - 1) return;

    __threadfence();   // acquire: all blocks' REDs visible

    float tot = 0.0f, ws = 0.0f, mx = 0.0f;
#pragma unroll
    for (int k = 0; k < NSEG / THREADS; k++) {
        const int i = k * THREADS + t;
        const unsigned long long p = d_bins[(size_t)i * STRIDE];
        d_bins[(size_t)i * STRIDE] = 0ull;          // reset for next replay
        const float        s = (float)(p & GMASK) * GINV;
        const unsigned int c = (unsigned int)(p >> 44);
        const float avg = s / fmaxf((float)c * (float)C_, 1.0f);
        tot += s;
        ws  += s * avg;
        mx   = fmaxf(mx, avg);
    }
#pragma unroll
    for (int o = 16; o > 0; o >>= 1) {
        tot += __shfl_xor_sync(0xffffffffu, tot, o);
        ws  += __shfl_xor_sync(0xffffffffu, ws,  o);
        mx   = fmaxf(mx, __shfl_xor_sync(0xffffffffu, mx, o));
    }
    if (lane == 0) { rtot[wid] = tot; rws[wid] = ws; rmx[wid] = mx; }
    __syncthreads();
    if (t == 0) {
        tot = rtot[0] + rtot[1] + rtot[2] + rtot[3];
        ws  = rws[0]  + rws[1]  + rws[2]  + rws[3];
        mx  = fmaxf(fmaxf(rmx[0], rmx[1]), fmaxf(rmx[2], rmx[3]));
        d_ticket = 0;                               // reset for next replay
        const float N = (float)B_ * (float)C_ * (float)HW_;
        const float weighted = (mx > 0.0f) ? (ws / mx) : 0.0f;   // BETA = 1
        out[0] = (tot + weighted) / N;
    }
}

extern "C" void kernel_launch(void* const* d_in, const int* in_sizes, int n_in,
                              void* d_out, int out_size)
{
    const float* inp = (const float*)d_in[0];
    const float* tgt = (const float*)d_in[1];
    const int*   msk = (const int*)  d_in[2];
    (void)in_sizes; (void)n_in; (void)out_size;

    cudaFuncSetAttribute(fused_kernel,
                         cudaFuncAttributeMaxDynamicSharedMemorySize, SMEM_TOTAL);
    fused_kernel<<<dim3(NBLKX, B_), THREADS, SMEM_TOTAL>>>(inp, tgt, msk,
                                                           (float*)d_out);
}